// round 10
// baseline (speedup 1.0000x reference)
#include <cuda_runtime.h>
#include <cuda_bf16.h>

#define BQ 8
#define NQ 8192
#define MK 2048
#define CC 256
#define EPSW 1e-8f
#define GSZ 8
#define NGROUP (MK / GSZ)     // 256 groups of 8 points -> 8-bit group id
#define KEYMASK 0xFFFFFF00u   // clear low 8 mantissa bits for the id

// Compact per-query result: (w0, w1, bitcast(i0 | i1<<16), bitcast(i2))
__device__ float4 g_wp[BQ * NQ];

// ---------------------------------------------------------------------------
// f32x2 packed helpers
// ---------------------------------------------------------------------------
typedef unsigned long long u64t;
__device__ __forceinline__ u64t fma2(u64t a, u64t b, u64t c) {
    u64t d; asm("fma.rn.f32x2 %0, %1, %2, %3;" : "=l"(d) : "l"(a), "l"(b), "l"(c));
    return d;
}
__device__ __forceinline__ u64t add2(u64t a, u64t b) {
    u64t d; asm("add.rn.f32x2 %0, %1, %2;" : "=l"(d) : "l"(a), "l"(b));
    return d;
}
__device__ __forceinline__ u64t mul2(u64t a, u64t b) {
    u64t d; asm("mul.rn.f32x2 %0, %1, %2;" : "=l"(d) : "l"(a), "l"(b));
    return d;
}
__device__ __forceinline__ u64t pack2(float lo, float hi) {
    u64t d; asm("mov.b64 %0, {%1, %2};" : "=l"(d) : "f"(lo), "f"(hi));
    return d;
}
__device__ __forceinline__ void unpack2(u64t v, float& lo, float& hi) {
    asm("mov.b64 {%0, %1}, %2;" : "=f"(lo), "=f"(hi) : "l"(v));
}

// ---------------------------------------------------------------------------
// Kernel 1: three_nn + weights.
// Hot loop: EXACT packed d^2 (24 math/group), 7-FMNMX min tree, then the
// group-min's low 8 mantissa bits are replaced by the group id (LOP3) and
// the resulting KEY goes through a pure 7-FMNMX top-4 bubble — keys carry
// their argmin, so no FSETP/SEL at all.
// Safety: masking exact d^2 (small values) perturbs keys by <= 255 ulp
// (~3e-8 abs) vs typical inter-group margins ~1e-3; keeping top-4 groups
// (not 3) makes a harmful demotion require two independent ~3e-8
// collisions (P ~ 1e-9/query). Finale: exact d^2 + exact top-3 over the
// 32 candidates, ascending index (jax lower-index tie-break).
// Block 128, 1 query/thread, grid (NQ/128, BQ) = 512 blocks.
// ---------------------------------------------------------------------------
__global__ void __launch_bounds__(128) nn_kernel(
    const float* __restrict__ unknown,   // (B, N, 3)
    const float* __restrict__ known)     // (B, M, 3)
{
    __shared__ float4 sXY[MK / 2];   // (x0,x1,y0,y1) per point-pair, 16 KB
    __shared__ float  sZ[MK];        // 8 KB

    const int b = blockIdx.y;
    {
        const float2* kb2 = (const float2*)(known + (size_t)b * MK * 3);
        for (int i = threadIdx.x; i < MK / 2; i += 128) {
            float2 p0 = kb2[i * 3 + 0];   // x0 y0
            float2 p1 = kb2[i * 3 + 1];   // z0 x1
            float2 p2 = kb2[i * 3 + 2];   // y1 z1
            sXY[i] = make_float4(p0.x, p1.y, p0.y, p2.x);
            sZ[2 * i]     = p1.x;
            sZ[2 * i + 1] = p2.y;
        }
    }
    __syncthreads();

    const int n = blockIdx.x * 128 + threadIdx.x;
    const float* u = unknown + ((size_t)b * NQ + n) * 3;
    const float ux = u[0], uy = u[1], uz = u[2];
    const u64t nux = pack2(-ux, -ux);
    const u64t nuy = pack2(-uy, -uy);
    const u64t nuz = pack2(-uz, -uz);

    // top-4 keys, ascending (key = masked group-min | group id)
    float k0 = 1e30f, k1 = 1e30f, k2 = 1e30f, k3 = 1e30f;

    const ulonglong2* pXY = (const ulonglong2*)sXY;
    const ulonglong2* pZ  = (const ulonglong2*)sZ;

#pragma unroll 4
    for (int g = 0; g < NGROUP; g++) {
        ulonglong2 A0 = pXY[4 * g + 0];
        ulonglong2 A1 = pXY[4 * g + 1];
        ulonglong2 A2 = pXY[4 * g + 2];
        ulonglong2 A3 = pXY[4 * g + 3];
        ulonglong2 Z0 = pZ[2 * g + 0];   // z[8g..8g+3]
        ulonglong2 Z1 = pZ[2 * g + 1];   // z[8g+4..8g+7]

        u64t dx0 = add2(A0.x, nux), dy0 = add2(A0.y, nuy), dz0 = add2(Z0.x, nuz);
        u64t dx1 = add2(A1.x, nux), dy1 = add2(A1.y, nuy), dz1 = add2(Z0.y, nuz);
        u64t dx2 = add2(A2.x, nux), dy2 = add2(A2.y, nuy), dz2 = add2(Z1.x, nuz);
        u64t dx3 = add2(A3.x, nux), dy3 = add2(A3.y, nuy), dz3 = add2(Z1.y, nuz);

        u64t a0 = fma2(dx0, dx0, fma2(dy0, dy0, mul2(dz0, dz0)));
        u64t a1 = fma2(dx1, dx1, fma2(dy1, dy1, mul2(dz1, dz1)));
        u64t a2 = fma2(dx2, dx2, fma2(dy2, dy2, mul2(dz2, dz2)));
        u64t a3 = fma2(dx3, dx3, fma2(dy3, dy3, mul2(dz3, dz3)));

        float s0, s1, s2, s3, s4, s5, s6, s7;
        unpack2(a0, s0, s1); unpack2(a1, s2, s3);
        unpack2(a2, s4, s5); unpack2(a3, s6, s7);

        float m = fminf(fminf(fminf(s0, s1), fminf(s2, s3)),
                        fminf(fminf(s4, s5), fminf(s6, s7)));

        // key = (exact group-min, low 8 mantissa bits -> group id)
        float key = __uint_as_float((__float_as_uint(m) & KEYMASK) | (unsigned)g);

        // pure FMNMX top-4 bubble (keys carry their id)
        float c0 = fmaxf(k0, key);  k0 = fminf(k0, key);
        float c1 = fmaxf(k1, c0);   k1 = fminf(k1, c0);
        float c2 = fmaxf(k2, c1);   k2 = fminf(k2, c1);
        k3 = fminf(k3, c2);
    }

    // Decode the 4 winning group ids; sort ascending (5-exchange network)
    int ga = __float_as_uint(k0) & 0xFF;
    int gb = __float_as_uint(k1) & 0xFF;
    int gc = __float_as_uint(k2) & 0xFF;
    int gd = __float_as_uint(k3) & 0xFF;
    { int lo = min(ga, gb), hi = max(ga, gb); ga = lo; gb = hi; }
    { int lo = min(gc, gd), hi = max(gc, gd); gc = lo; gd = hi; }
    { int lo = min(ga, gc), hi = max(ga, gc); ga = lo; gc = hi; }
    { int lo = min(gb, gd), hi = max(gb, gd); gb = lo; gd = hi; }
    { int lo = min(gb, gc), hi = max(gb, gc); gb = lo; gc = hi; }
    int grp[4] = { ga, gb, gc, gd };

    // Finale: exact top-3 over the 32 candidate points.
    float d0 = 1e30f, d1 = 1e30f, d2v = 1e30f;
    int   i0 = 0, i1 = 0, i2 = 0;
#pragma unroll
    for (int t = 0; t < 4; t++) {
        const int mb = grp[t] * GSZ;
#pragma unroll
        for (int k = 0; k < GSZ; k++) {
            const int m = mb + k;
            const int p = m >> 1, h = m & 1;
            float4 XY = sXY[p];
            float kx = h ? XY.y : XY.x;
            float ky = h ? XY.w : XY.z;
            float kz = sZ[m];
            float dx = kx - ux, dy = ky - uy, dz = kz - uz;
            float d2 = fmaf(dx, dx, fmaf(dy, dy, dz * dz));
            bool c0b = d2 < d0, c1b = d2 < d1, c2b = d2 < d2v;
            float t0 = c0b ? d2 : d0;
            float t1 = c0b ? d0 : (c1b ? d2 : d1);
            float t2 = c1b ? d1 : (c2b ? d2 : d2v);
            int   j0 = c0b ? m  : i0;
            int   j1 = c0b ? i0 : (c1b ? m  : i1);
            int   j2 = c1b ? i1 : (c2b ? m  : i2);
            d0 = t0; d1 = t1; d2v = t2;
            i0 = j0; i1 = j1; i2 = j2;
        }
    }

    const float r0 = 1.0f / (d0 + EPSW);
    const float r1 = 1.0f / (d1 + EPSW);
    const float r2 = 1.0f / (d2v + EPSW);
    const float s  = 1.0f / (r0 + r1 + r2);
    g_wp[(size_t)b * NQ + n] =
        make_float4(r0 * s, r1 * s,
                    __int_as_float(i0 | (i1 << 16)),
                    __int_as_float(i2));
}

// ---------------------------------------------------------------------------
// Kernel 2: three_interpolate (unchanged — measured local floor ~33.5 us).
// Grid (CC/4, BQ) = 512 blocks, block 256, smem rowsT[m][c0..c0+3] (32 KB).
// ---------------------------------------------------------------------------
#define CG 4

__global__ void __launch_bounds__(256) interp_kernel(
    const float* __restrict__ feats,     // (B, C, M)
    float* __restrict__ out)             // (B, C, N)
{
    __shared__ float rowsT[MK * CG];     // 32 KB

    const int b  = blockIdx.y;
    const int c0 = blockIdx.x * CG;

    {
        const float* fp = feats + ((size_t)b * CC + c0) * MK;
#pragma unroll
        for (int it = 0; it < MK / 256; it++) {
            const int m = it * 256 + threadIdx.x;
            float a  = fp[m];
            float bb = fp[MK + m];
            float c  = fp[2 * MK + m];
            float d  = fp[3 * MK + m];
            *(float4*)&rowsT[m * 4] = make_float4(a, bb, c, d);
        }
    }
    __syncthreads();

    const float4* wp = (const float4*)&g_wp[(size_t)b * NQ];
    float* outp = out + ((size_t)b * CC + c0) * NQ;

    for (int it = 0; it < NQ / 1024; it++) {   // 8 iters
        const int n0 = it * 1024 + threadIdx.x * 4;

        float4 W0 = wp[n0 + 0];
        float4 W1 = wp[n0 + 1];
        float4 W2 = wp[n0 + 2];
        float4 W3 = wp[n0 + 3];

        int j[12];
        {
            unsigned pk0 = __float_as_uint(W0.z);
            unsigned pk1 = __float_as_uint(W1.z);
            unsigned pk2 = __float_as_uint(W2.z);
            unsigned pk3 = __float_as_uint(W3.z);
            j[0]  = pk0 & 0xFFFF; j[1]  = pk0 >> 16; j[2]  = __float_as_uint(W0.w);
            j[3]  = pk1 & 0xFFFF; j[4]  = pk1 >> 16; j[5]  = __float_as_uint(W1.w);
            j[6]  = pk2 & 0xFFFF; j[7]  = pk2 >> 16; j[8]  = __float_as_uint(W2.w);
            j[9]  = pk3 & 0xFFFF; j[10] = pk3 >> 16; j[11] = __float_as_uint(W3.w);
        }

        ulonglong2 f[12];
#pragma unroll
        for (int t = 0; t < 12; t++)
            f[t] = *(const ulonglong2*)&rowsT[j[t] * 4];

        float vq[4][4];   // [query][channel]
        const float4 Wv[4] = { W0, W1, W2, W3 };
#pragma unroll
        for (int q = 0; q < 4; q++) {
            float w0 = Wv[q].x, w1 = Wv[q].y;
            float w2 = 1.0f - w0 - w1;
            u64t w0p = pack2(w0, w0);
            u64t w1p = pack2(w1, w1);
            u64t w2p = pack2(w2, w2);
            u64t lo = fma2(w0p, f[3*q].x, fma2(w1p, f[3*q+1].x, mul2(w2p, f[3*q+2].x)));
            u64t hi = fma2(w0p, f[3*q].y, fma2(w1p, f[3*q+1].y, mul2(w2p, f[3*q+2].y)));
            unpack2(lo, vq[q][0], vq[q][1]);
            unpack2(hi, vq[q][2], vq[q][3]);
        }

#pragma unroll
        for (int c = 0; c < CG; c++) {
            float4 v = make_float4(vq[0][c], vq[1][c], vq[2][c], vq[3][c]);
            *(float4*)(outp + (size_t)c * NQ + n0) = v;
        }
    }
}

// ---------------------------------------------------------------------------
// Launch
// ---------------------------------------------------------------------------
extern "C" void kernel_launch(void* const* d_in, const int* in_sizes, int n_in,
                              void* d_out, int out_size)
{
    const float* unknown = (const float*)d_in[0];   // (8, 8192, 3)
    const float* known   = (const float*)d_in[1];   // (8, 2048, 3)
    const float* feats   = (const float*)d_in[2];   // (8, 256, 2048)
    float* out = (float*)d_out;                     // (8, 256, 8192)

    dim3 g1(NQ / 128, BQ);
    nn_kernel<<<g1, 128>>>(unknown, known);

    dim3 g2(CC / CG, BQ);
    interp_kernel<<<g2, 256>>>(feats, out);
}